// round 15
// baseline (speedup 1.0000x reference)
#include <cuda_runtime.h>

// ---------------------------------------------------------------------------
// QConv2d: out = (uc2 (x) ux (x) uy) . rho . (uc2 (x) ux (x) uy)^T
//   row index r = f*64 + i*8 + j : ux acts on digit i, uy acts on digit j.
// Two 8x8-block passes on a padded 128x136 smem tile (256 threads, 2 CTA/SM):
//   Pass A (fused gmem load, MLP-batched): (j,j') blocks, O = uy . X . uy^T
//   Pass B: (i,i') blocks, O = ux . X . ux^T
// v-major uc2 . M . uc2^T epilogue. Streaming cache hints: rho via ld.nc.cs,
// out via st.cs (write-once data, keep L1 for smem-adjacent traffic).
// Weights written redundantly by every warp (same values) -> no init barrier.
// ---------------------------------------------------------------------------

#define PSTR 136
#define SM_UYD 17408   // u64 uy_dup[64]
#define SM_UXD 17536   // u64 ux_dup[64]
#define SM_UYS 17664   // float uy[64]
#define SM_UXS 17728   // float ux[64]
#define SM_UC  17792   // float uc2[8]
#define SMEM_BYTES (17800 * 4)   // 71200 B -> 2 CTAs/SM

typedef unsigned long long u64t;

__device__ __forceinline__ u64t pk2(float lo, float hi) {
    u64t r; asm("mov.b64 %0, {%1,%2};" : "=l"(r) : "f"(lo), "f"(hi)); return r;
}
__device__ __forceinline__ u64t fma2(u64t a, u64t b, u64t c) {
    u64t d; asm("fma.rn.f32x2 %0, %1, %2, %3;" : "=l"(d) : "l"(a), "l"(b), "l"(c));
    return d;
}
__device__ __forceinline__ u64t mul2(u64t a, u64t b) {
    u64t d; asm("mul.rn.f32x2 %0, %1, %2;" : "=l"(d) : "l"(a), "l"(b));
    return d;
}
__device__ __forceinline__ void upk2(u64t v, float& lo, float& hi) {
    asm("mov.b64 {%0,%1}, %2;" : "=f"(lo), "=f"(hi) : "l"(v));
}
__device__ __forceinline__ u64t lds64(const u64t* p) {
    u64t r; asm("ld.shared.b64 %0, [%1];" : "=l"(r) : "l"((size_t)__cvta_generic_to_shared(p)));
    return r;
}
__device__ __forceinline__ float4 ldg128_nc_cs(const float4* p) {
    float4 v;
    asm("ld.global.nc.cs.v4.f32 {%0,%1,%2,%3}, [%4];"
        : "=f"(v.x), "=f"(v.y), "=f"(v.z), "=f"(v.w) : "l"(p));
    return v;
}
__device__ __forceinline__ void stg128_cs(float4* p, float4 v) {
    asm volatile("st.global.cs.v4.f32 [%0], {%1,%2,%3,%4};"
                 :: "l"(p), "f"(v.x), "f"(v.y), "f"(v.z), "f"(v.w) : "memory");
}

__global__ void __launch_bounds__(256, 2)
qconv_kernel(const float* __restrict__ rho,
             const float* __restrict__ ux,
             const float* __restrict__ uy,
             const float* __restrict__ uc,
             float* __restrict__ out)
{
    extern __shared__ float s[];
    float* buf = s;
    const int b = blockIdx.x;
    const int t = threadIdx.x;
    const int lane = t & 31;

    // Every warp redundantly writes the full weight tables (identical values:
    // benign race), then __syncwarp -> no CTA barrier needed before use.
    {
        // lane 0..31 covers 64 entries in 2 steps
        #pragma unroll
        for (int k = 0; k < 2; ++k) {
            int q = lane + k * 32;
            float vy = __ldg(uy + q), vx = __ldg(ux + q);
            s[SM_UYS + q] = vy;  s[SM_UXS + q] = vx;
            ((u64t*)(s + SM_UYD))[q] = pk2(vy, vy);
            ((u64t*)(s + SM_UXD))[q] = pk2(vx, vx);
        }
        if (lane < 8)
            s[SM_UC + lane] = __ldg(uc + (lane >> 1) * 4 + 2 + (lane & 1));
        __syncwarp();
    }

    // ====================== Pass A: (j,j') blocks, uy both sides ===========
    {
        const int rb = t >> 4, cb = t & 15;
        const float* src = rho + (size_t)b * 16384 + (size_t)rb * 8 * 128 + cb * 8;
        const u64t* uyd = (const u64t*)(s + SM_UYD);

        // phase 1: batch-issue all 8 first-half loads (MLP >= 8)
        float4 q0[8];
        #pragma unroll
        for (int j = 0; j < 8; ++j)
            q0[j] = ldg128_nc_cs((const float4*)(src + j * 128));

        // phase 2: issue second-half loads while consuming the first batch
        u64t Yp[8][4];
        float4 q1[8];
        #pragma unroll
        for (int j = 0; j < 8; ++j) {
            q1[j] = ldg128_nc_cs((const float4*)(src + j * 128 + 4));
            u64t xpa = pk2(q0[j].x, q0[j].y);
            u64t xpb = pk2(q0[j].z, q0[j].w);
            if (j == 0) {
                #pragma unroll
                for (int a = 0; a < 8; ++a) {
                    u64t u = lds64(uyd + a * 8);
                    Yp[a][0] = mul2(u, xpa);
                    Yp[a][1] = mul2(u, xpb);
                }
            } else {
                #pragma unroll
                for (int a = 0; a < 8; ++a) {
                    u64t u = lds64(uyd + a * 8 + j);
                    Yp[a][0] = fma2(u, xpa, Yp[a][0]);
                    Yp[a][1] = fma2(u, xpb, Yp[a][1]);
                }
            }
        }
        // phase 3: consume second batch
        #pragma unroll
        for (int j = 0; j < 8; ++j) {
            u64t xpc = pk2(q1[j].x, q1[j].y);
            u64t xpd = pk2(q1[j].z, q1[j].w);
            if (j == 0) {
                #pragma unroll
                for (int a = 0; a < 8; ++a) {
                    u64t u = lds64(uyd + a * 8);
                    Yp[a][2] = mul2(u, xpc);
                    Yp[a][3] = mul2(u, xpd);
                }
            } else {
                #pragma unroll
                for (int a = 0; a < 8; ++a) {
                    u64t u = lds64(uyd + a * 8 + j);
                    Yp[a][2] = fma2(u, xpc, Yp[a][2]);
                    Yp[a][3] = fma2(u, xpd, Yp[a][3]);
                }
            }
        }
        float Ys[8][8];
        #pragma unroll
        for (int a = 0; a < 8; ++a)
            #pragma unroll
            for (int jp = 0; jp < 4; ++jp)
                upk2(Yp[a][jp], Ys[a][2*jp], Ys[a][2*jp+1]);

        // stage 2: O[a][b] = sum_j' Ys[a][j'] * uy[b][j']
        const float* uys = s + SM_UYS;
        float* dst = buf + (rb * 8) * PSTR + cb * 8;
        #pragma unroll
        for (int h = 0; h < 2; ++h) {
            float Oc[8][4];
            #pragma unroll
            for (int b4 = 0; b4 < 4; ++b4) {
                float sc = uys[(h * 4 + b4) * 8];
                #pragma unroll
                for (int a = 0; a < 8; ++a) Oc[a][b4] = Ys[a][0] * sc;
            }
            #pragma unroll
            for (int jq = 1; jq < 8; ++jq) {
                #pragma unroll
                for (int b4 = 0; b4 < 4; ++b4) {
                    float sc = uys[(h * 4 + b4) * 8 + jq];
                    #pragma unroll
                    for (int a = 0; a < 8; ++a)
                        Oc[a][b4] = fmaf(Ys[a][jq], sc, Oc[a][b4]);
                }
            }
            #pragma unroll
            for (int a = 0; a < 8; ++a)
                *(float4*)(dst + a * PSTR + h * 4) =
                    make_float4(Oc[a][0], Oc[a][1], Oc[a][2], Oc[a][3]);
        }
    }
    __syncthreads();

    // ====================== Pass B: (i,i') blocks, ux both sides ===========
    {
        const int rb2 = t >> 4, cb2 = t & 15;
        const int f  = rb2 >> 3, j  = rb2 & 7;
        const int fp = cb2 >> 3, jp_ = cb2 & 7;
        float* base = buf + (f * 64 + j) * PSTR + fp * 64 + jp_;
        const u64t* uxd = (const u64t*)(s + SM_UXD);

        u64t Zp[8][4];
        {
            float x[8];
            #pragma unroll
            for (int ii = 0; ii < 8; ++ii) x[ii] = base[ii * 8];
            u64t xp[4] = { pk2(x[0],x[1]), pk2(x[2],x[3]), pk2(x[4],x[5]), pk2(x[6],x[7]) };
            #pragma unroll
            for (int a = 0; a < 8; ++a) {
                u64t u = lds64(uxd + a * 8);
                #pragma unroll
                for (int ip = 0; ip < 4; ++ip) Zp[a][ip] = mul2(u, xp[ip]);
            }
        }
        #pragma unroll
        for (int i = 1; i < 8; ++i) {
            float x[8];
            #pragma unroll
            for (int ii = 0; ii < 8; ++ii) x[ii] = base[i * 8 * PSTR + ii * 8];
            u64t xp[4] = { pk2(x[0],x[1]), pk2(x[2],x[3]), pk2(x[4],x[5]), pk2(x[6],x[7]) };
            #pragma unroll
            for (int a = 0; a < 8; ++a) {
                u64t u = lds64(uxd + a * 8 + i);
                #pragma unroll
                for (int ip = 0; ip < 4; ++ip) Zp[a][ip] = fma2(u, xp[ip], Zp[a][ip]);
            }
        }
        float Zs[8][8];
        #pragma unroll
        for (int a = 0; a < 8; ++a)
            #pragma unroll
            for (int ip = 0; ip < 4; ++ip)
                upk2(Zp[a][ip], Zs[a][2*ip], Zs[a][2*ip+1]);

        const float* uxs = s + SM_UXS;
        #pragma unroll
        for (int h = 0; h < 2; ++h) {
            float Oc[8][4];
            #pragma unroll
            for (int b4 = 0; b4 < 4; ++b4) {
                float sc = uxs[(h * 4 + b4) * 8];
                #pragma unroll
                for (int a = 0; a < 8; ++a) Oc[a][b4] = Zs[a][0] * sc;
            }
            #pragma unroll
            for (int iq = 1; iq < 8; ++iq) {
                #pragma unroll
                for (int b4 = 0; b4 < 4; ++b4) {
                    float sc = uxs[(h * 4 + b4) * 8 + iq];
                    #pragma unroll
                    for (int a = 0; a < 8; ++a)
                        Oc[a][b4] = fmaf(Zs[a][iq], sc, Oc[a][b4]);
                }
            }
            #pragma unroll
            for (int a = 0; a < 8; ++a)
                #pragma unroll
                for (int b4 = 0; b4 < 4; ++b4)
                    base[a * 8 * PSTR + (h * 4 + b4) * 8] = Oc[a][b4];
        }
    }
    __syncthreads();

    // ===== v-major epilogue: load each M block once, emit all 4 g rows ======
    {
        const int wid = t >> 5;
        const int vp0 = (lane & 15) * 4;
        const int hi  = lane >> 4;               // selects g' = 2*it + hi
        float* outb = out + (size_t)b * 65536;

        u64t c0d[4], c1d[4];
        #pragma unroll
        for (int g = 0; g < 4; ++g) {
            float a0 = s[SM_UC + g * 2], a1 = s[SM_UC + g * 2 + 1];
            c0d[g] = pk2(a0, a0);
            c1d[g] = pk2(a1, a1);
        }

        #pragma unroll 2
        for (int rr = 0; rr < 8; ++rr) {
            const int v = wid * 8 + rr;          // 0..63
            const float* row0 = buf + v * PSTR;          // f = 0
            const float* row1 = buf + (64 + v) * PSTR;   // f = 1
            float4 q00 = *(const float4*)(row0 + vp0);        // f'=0
            float4 q01 = *(const float4*)(row0 + 64 + vp0);   // f'=1
            float4 q10 = *(const float4*)(row1 + vp0);
            float4 q11 = *(const float4*)(row1 + 64 + vp0);
            u64t m00a = ((u64t*)&q00)[0], m00b = ((u64t*)&q00)[1];
            u64t m01a = ((u64t*)&q01)[0], m01b = ((u64t*)&q01)[1];
            u64t m10a = ((u64t*)&q10)[0], m10b = ((u64t*)&q10)[1];
            u64t m11a = ((u64t*)&q11)[0], m11b = ((u64t*)&q11)[1];

            #pragma unroll
            for (int g = 0; g < 4; ++g) {
                u64t t0a = fma2(c1d[g], m10a, mul2(c0d[g], m00a));
                u64t t0b = fma2(c1d[g], m10b, mul2(c0d[g], m00b));
                u64t t1a = fma2(c1d[g], m11a, mul2(c0d[g], m01a));
                u64t t1b = fma2(c1d[g], m11b, mul2(c0d[g], m01b));
                float* orow = outb + (g * 64 + v) * 256;
                #pragma unroll
                for (int it = 0; it < 2; ++it) {
                    const int gp = (it << 1) | hi;
                    u64t oa = fma2(c1d[gp], t1a, mul2(c0d[gp], t0a));
                    u64t ob = fma2(c1d[gp], t1b, mul2(c0d[gp], t0b));
                    float4 o;
                    ((u64t*)&o)[0] = oa;
                    ((u64t*)&o)[1] = ob;
                    stg128_cs((float4*)(orow + gp * 64 + vp0), o);
                }
            }
        }
    }
}

extern "C" void kernel_launch(void* const* d_in, const int* in_sizes, int n_in,
                              void* d_out, int out_size) {
    const float* rho = (const float*)d_in[0];
    const float* ux  = (const float*)d_in[1];
    const float* uy  = (const float*)d_in[2];
    const float* uc  = (const float*)d_in[3];
    float* out = (float*)d_out;

    const int B = in_sizes[0] >> 14;   // elements / (128*128)

    cudaFuncSetAttribute(qconv_kernel,
                         cudaFuncAttributeMaxDynamicSharedMemorySize, SMEM_BYTES);
    qconv_kernel<<<B, 256, SMEM_BYTES>>>(rho, ux, uy, uc, out);
}